// round 6
// baseline (speedup 1.0000x reference)
#include <cuda_runtime.h>
#include <cstdint>
#include <cstddef>

typedef unsigned long long ull;

#define DEV_INLINE __device__ __forceinline__

DEV_INLINE ull fma2(ull a, ull b, ull c) {
    ull d; asm("fma.rn.f32x2 %0, %1, %2, %3;" : "=l"(d) : "l"(a), "l"(b), "l"(c)); return d;
}
DEV_INLINE ull pack2(float lo, float hi) {
    ull r; asm("mov.b64 %0, {%1, %2};" : "=l"(r) : "f"(lo), "f"(hi)); return r;
}
DEV_INLINE float2 unpk(ull v) {
    float2 f; asm("mov.b64 {%0, %1}, %2;" : "=f"(f.x), "=f"(f.y) : "l"(v)); return f;
}

// ---------------------------------------------------------------------------
// Problem constants
// ---------------------------------------------------------------------------
#define BB 256   // batch
#define TT 512   // time
#define HH 256   // hidden
#define G3 768   // 3*H
#define KP 80    // padded IN_DIM (75 -> 80)

// ---------------------------------------------------------------------------
// Scratch (static device arrays; cudaMalloc forbidden)
// ---------------------------------------------------------------------------
__device__ float g_xg[(size_t)BB * TT * G3];    // input-gate preactivations
__device__ float g_out0[(size_t)BB * TT * HH];  // layer-0 output sequence
__device__ float g_hT[BB * HH];                 // final hidden of layer 1
__device__ float g_xpad[(size_t)BB * TT * KP];  // x padded to K=80
__device__ float g_wpad[G3 * KP];               // W_ih0 padded to K=80

// ---------------------------------------------------------------------------
// Padding pre-kernels
// ---------------------------------------------------------------------------
__global__ void pad_k75(const float* __restrict__ src, float* __restrict__ dst, int rows)
{
    int idx = blockIdx.x * blockDim.x + threadIdx.x;
    if (idx >= rows * KP) return;
    int r = idx / KP, c = idx - r * KP;
    dst[idx] = (c < 75) ? src[r * 75 + c] : 0.f;
}

// ---------------------------------------------------------------------------
// GEMM: C[M][N] = A[M][K] @ W[N][K]^T + bias[N]   (K % 4 == 0 required)
// 128x128 tile, BK=16, 256 threads, 8x8 microtile, f32x2 FMAs.  (unchanged)
// ---------------------------------------------------------------------------
__global__ __launch_bounds__(256, 2) void gemm_tn_bias(
    const float* __restrict__ A, const float* __restrict__ W,
    const float* __restrict__ bias, float* __restrict__ C,
    int M, int N, int K)
{
    __shared__ ull As2[16][130];
    __shared__ ull Bs2[16][68];

    const int tid = threadIdx.x;
    const int tm = tid >> 4;
    const int tn = tid & 15;
    const int mb = blockIdx.x * 128;
    const int nb = blockIdx.y * 128;

    const int lr = tid >> 1;
    const int lh = (tid & 1) * 8;
    const int pp = tid >> 2;
    const int pq = (tid & 3) * 4;

    ull acc[8][4];
#pragma unroll
    for (int i = 0; i < 8; ++i)
#pragma unroll
        for (int j = 0; j < 4; ++j) acc[i][j] = 0ull;

    for (int k0 = 0; k0 < K; k0 += 16) {
        const float* ap = A + (size_t)(mb + lr) * K + k0 + lh;
        float4 v0 = *(const float4*)(ap);
        float4 v1 = *(const float4*)(ap + 4);
        As2[lh + 0][lr] = pack2(v0.x, v0.x);
        As2[lh + 1][lr] = pack2(v0.y, v0.y);
        As2[lh + 2][lr] = pack2(v0.z, v0.z);
        As2[lh + 3][lr] = pack2(v0.w, v0.w);
        As2[lh + 4][lr] = pack2(v1.x, v1.x);
        As2[lh + 5][lr] = pack2(v1.y, v1.y);
        As2[lh + 6][lr] = pack2(v1.z, v1.z);
        As2[lh + 7][lr] = pack2(v1.w, v1.w);
        const float* wp0 = W + (size_t)(nb + 2 * pp) * K + k0 + pq;
        const float* wp1 = wp0 + K;
        float4 w0 = *(const float4*)wp0;
        float4 w1 = *(const float4*)wp1;
        Bs2[pq + 0][pp] = pack2(w0.x, w1.x);
        Bs2[pq + 1][pp] = pack2(w0.y, w1.y);
        Bs2[pq + 2][pp] = pack2(w0.z, w1.z);
        Bs2[pq + 3][pp] = pack2(w0.w, w1.w);
        __syncthreads();
#pragma unroll
        for (int k = 0; k < 16; ++k) {
            ulonglong2 a01 = *(const ulonglong2*)&As2[k][8 * tm];
            ulonglong2 a23 = *(const ulonglong2*)&As2[k][8 * tm + 2];
            ulonglong2 a45 = *(const ulonglong2*)&As2[k][8 * tm + 4];
            ulonglong2 a67 = *(const ulonglong2*)&As2[k][8 * tm + 6];
            ulonglong2 b01 = *(const ulonglong2*)&Bs2[k][2 * tn];
            ulonglong2 b23 = *(const ulonglong2*)&Bs2[k][32 + 2 * tn];
            ull b0 = b01.x, b1 = b01.y, b2 = b23.x, b3 = b23.y;
            acc[0][0] = fma2(a01.x, b0, acc[0][0]); acc[0][1] = fma2(a01.x, b1, acc[0][1]);
            acc[0][2] = fma2(a01.x, b2, acc[0][2]); acc[0][3] = fma2(a01.x, b3, acc[0][3]);
            acc[1][0] = fma2(a01.y, b0, acc[1][0]); acc[1][1] = fma2(a01.y, b1, acc[1][1]);
            acc[1][2] = fma2(a01.y, b2, acc[1][2]); acc[1][3] = fma2(a01.y, b3, acc[1][3]);
            acc[2][0] = fma2(a23.x, b0, acc[2][0]); acc[2][1] = fma2(a23.x, b1, acc[2][1]);
            acc[2][2] = fma2(a23.x, b2, acc[2][2]); acc[2][3] = fma2(a23.x, b3, acc[2][3]);
            acc[3][0] = fma2(a23.y, b0, acc[3][0]); acc[3][1] = fma2(a23.y, b1, acc[3][1]);
            acc[3][2] = fma2(a23.y, b2, acc[3][2]); acc[3][3] = fma2(a23.y, b3, acc[3][3]);
            acc[4][0] = fma2(a45.x, b0, acc[4][0]); acc[4][1] = fma2(a45.x, b1, acc[4][1]);
            acc[4][2] = fma2(a45.x, b2, acc[4][2]); acc[4][3] = fma2(a45.x, b3, acc[4][3]);
            acc[5][0] = fma2(a45.y, b0, acc[5][0]); acc[5][1] = fma2(a45.y, b1, acc[5][1]);
            acc[5][2] = fma2(a45.y, b2, acc[5][2]); acc[5][3] = fma2(a45.y, b3, acc[5][3]);
            acc[6][0] = fma2(a67.x, b0, acc[6][0]); acc[6][1] = fma2(a67.x, b1, acc[6][1]);
            acc[6][2] = fma2(a67.x, b2, acc[6][2]); acc[6][3] = fma2(a67.x, b3, acc[6][3]);
            acc[7][0] = fma2(a67.y, b0, acc[7][0]); acc[7][1] = fma2(a67.y, b1, acc[7][1]);
            acc[7][2] = fma2(a67.y, b2, acc[7][2]); acc[7][3] = fma2(a67.y, b3, acc[7][3]);
        }
        __syncthreads();
    }

    float4 bb0 = *(const float4*)(bias + nb + 4 * tn);
    float4 bb1 = *(const float4*)(bias + nb + 64 + 4 * tn);
#pragma unroll
    for (int i = 0; i < 8; ++i) {
        float* crow = C + (size_t)(mb + 8 * tm + i) * N + nb;
        float2 p0 = unpk(acc[i][0]), p1 = unpk(acc[i][1]);
        float2 p2 = unpk(acc[i][2]), p3 = unpk(acc[i][3]);
        float4 o0; o0.x = p0.x + bb0.x; o0.y = p0.y + bb0.y; o0.z = p1.x + bb0.z; o0.w = p1.y + bb0.w;
        float4 o1; o1.x = p2.x + bb1.x; o1.y = p2.y + bb1.y; o1.z = p3.x + bb1.z; o1.w = p3.y + bb1.w;
        *(float4*)(crow + 4 * tn)      = o0;
        *(float4*)(crow + 64 + 4 * tn) = o1;
    }
}

// ---------------------------------------------------------------------------
// GRU recurrence: 32 clusters x 4 CTAs, 1024 threads/CTA (8 warps/SMSP).
// Thread = (h_local 0..63) x (bp 0..3) x (kq 0..3):
//   1 hidden unit, 2 batches (bp, bp+4), k-quarter kq.
// Smem layout: rows split into 4 quarters of 68 floats (64 data + 4 pad),
// row stride 272 -> W loads 1 wavefront, h loads 2 (= data minimum).
// Butterfly shfl_xor(1,2) merges the 4 k-quarters; lanes kq<2 emit outputs.
// ---------------------------------------------------------------------------
#define QSTR 68
#define RSTR 272                       // 4 * QSTR
#define REC_W_FLOATS (192 * RSTR)      // 52224
#define REC_SMEM ((192 * RSTR + 2 * 8 * RSTR) * 4)   // 226304 B

DEV_INLINE unsigned ctarank() { unsigned r; asm("mov.u32 %0, %%cluster_ctarank;" : "=r"(r)); return r; }
DEV_INLINE unsigned s2u(const void* p) {
    unsigned a;
    asm("{ .reg .u64 t; cvta.to.shared.u64 t, %1; cvt.u32.u64 %0, t; }" : "=r"(a) : "l"(p));
    return a;
}
DEV_INLINE unsigned mapa_(unsigned a, unsigned r) {
    unsigned o; asm("mapa.shared::cluster.u32 %0, %1, %2;" : "=r"(o) : "r"(a), "r"(r)); return o;
}
DEV_INLINE void st_cluster_u32(unsigned addr, unsigned v) {
    asm volatile("st.shared::cluster.u32 [%0], %1;" :: "r"(addr), "r"(v) : "memory");
}
DEV_INLINE void cl_arrive() { asm volatile("barrier.cluster.arrive.aligned;" ::: "memory"); }
DEV_INLINE void cl_wait()   { asm volatile("barrier.cluster.wait.aligned;"   ::: "memory"); }

__global__ __launch_bounds__(1024, 1) void gru_rec(
    const float* __restrict__ xg, const float* __restrict__ W_hh,
    const float* __restrict__ b_hh, float* __restrict__ out_seq,
    float* __restrict__ hT, int layer0)
{
    extern __shared__ float smem[];
    float* w = smem;                        // [192 rows][272]
    float* hbase = smem + REC_W_FLOATS;     // [2 bufs][8 batches][272]

    const int tid = threadIdx.x;
    const unsigned rank = ctarank();
    const int cid = blockIdx.x >> 2;        // cluster 0..31
    const int h_local = tid >> 4;           // 0..63
    const int bp = (tid >> 2) & 3;          // 0..3
    const int kq = tid & 3;                 // k-quarter 0..3
    const int h_glob = (int)rank * 64 + h_local;
    const int sel = kq & 1;
    const int bsel = bp + 4 * sel;          // batch this lane finalizes
    const int bglob = cid * 8 + bsel;
    const bool out_lane = (kq < 2);
    // h position inside a 272-float batch row (quarter q = h_glob>>6 == rank)
    const int hpos = (int)rank * QSTR + (h_glob & 63);

    // Load W_hh slice: smem row g*64+h <- global row g*256 + rank*64 + h,
    // column k stored at quarter (k>>6)*68 + (k&63).
    for (int i = tid; i < 192 * 64; i += 1024) {
        int row = i >> 6, k4i = i & 63;          // k4i = k/4
        int grow = (row >> 6) * 256 + (int)rank * 64 + (row & 63);
        float4 v = ((const float4*)W_hh)[(size_t)grow * 64 + k4i];
        int pos = row * RSTR + (k4i >> 4) * QSTR + (k4i & 15) * 4;
        *(float4*)(w + pos) = v;
    }
    for (int i = tid; i < 8 * RSTR; i += 1024) hbase[i] = 0.f;  // buf0 = 0

    const float bh_r = b_hh[h_glob];
    const float bh_z = b_hh[256 + h_glob];
    const float bh_n = b_hh[512 + h_glob];

    __syncthreads();
    cl_arrive(); cl_wait();

    unsigned hbase_u = s2u(hbase);
    unsigned pb[4];
#pragma unroll
    for (int q = 0; q < 4; ++q) pb[q] = mapa_(hbase_u, (unsigned)q);

    const float* wq = w + h_local * RSTR + kq * QSTR;     // gate r row; +64*RSTR z; +128*RSTR n
    const float* hq = hbase + bp * RSTR + kq * QSTR;      // batch bp, this quarter

    const float* xrow = xg + (size_t)bglob * TT * G3;
    float xr = xrow[h_glob], xz = xrow[256 + h_glob], xn = xrow[512 + h_glob];

    int p = 0;
    for (int t = 0; t < TT; ++t) {
        const float* h0r = hq + p * (8 * RSTR);   // batch bp
        const float* h1r = h0r + 4 * RSTR;        // batch bp+4

        ull ar0 = 0, az0 = 0, an0 = 0, ar1 = 0, az1 = 0, an1 = 0;
#pragma unroll 4
        for (int i = 0; i < 16; ++i) {
            ulonglong2 h0v = *(const ulonglong2*)(h0r + 4 * i);
            ulonglong2 h1v = *(const ulonglong2*)(h1r + 4 * i);
            ulonglong2 wrv = *(const ulonglong2*)(wq + 4 * i);
            ulonglong2 wzv = *(const ulonglong2*)(wq + 64 * RSTR + 4 * i);
            ulonglong2 wnv = *(const ulonglong2*)(wq + 128 * RSTR + 4 * i);
            ar0 = fma2(wrv.x, h0v.x, ar0); ar0 = fma2(wrv.y, h0v.y, ar0);
            az0 = fma2(wzv.x, h0v.x, az0); az0 = fma2(wzv.y, h0v.y, az0);
            an0 = fma2(wnv.x, h0v.x, an0); an0 = fma2(wnv.y, h0v.y, an0);
            ar1 = fma2(wrv.x, h1v.x, ar1); ar1 = fma2(wrv.y, h1v.y, ar1);
            az1 = fma2(wzv.x, h1v.x, az1); az1 = fma2(wzv.y, h1v.y, az1);
            an1 = fma2(wnv.x, h1v.x, an1); an1 = fma2(wnv.y, h1v.y, an1);
        }
        float2 s;
        s = unpk(ar0); float fr0 = s.x + s.y;
        s = unpk(az0); float fz0 = s.x + s.y;
        s = unpk(an0); float fn0 = s.x + s.y;
        s = unpk(ar1); float fr1 = s.x + s.y;
        s = unpk(az1); float fz1 = s.x + s.y;
        s = unpk(an1); float fn1 = s.x + s.y;

        // butterfly over the 4 kq lanes (lane bits 0-1)
        fr0 += __shfl_xor_sync(0xffffffffu, fr0, 1);
        fz0 += __shfl_xor_sync(0xffffffffu, fz0, 1);
        fn0 += __shfl_xor_sync(0xffffffffu, fn0, 1);
        fr1 += __shfl_xor_sync(0xffffffffu, fr1, 1);
        fz1 += __shfl_xor_sync(0xffffffffu, fz1, 1);
        fn1 += __shfl_xor_sync(0xffffffffu, fn1, 1);
        fr0 += __shfl_xor_sync(0xffffffffu, fr0, 2);
        fz0 += __shfl_xor_sync(0xffffffffu, fz0, 2);
        fn0 += __shfl_xor_sync(0xffffffffu, fn0, 2);
        fr1 += __shfl_xor_sync(0xffffffffu, fr1, 2);
        fz1 += __shfl_xor_sync(0xffffffffu, fz1, 2);
        fn1 += __shfl_xor_sync(0xffffffffu, fn1, 2);

        float hr = sel ? fr1 : fr0;
        float hz = sel ? fz1 : fz0;
        float hn = sel ? fn1 : fn0;

        float hp = hbase[(p * 8 + bsel) * RSTR + hpos];

        float r = 1.f / (1.f + __expf(-(xr + bh_r + hr)));
        float z = 1.f / (1.f + __expf(-(xz + bh_z + hz)));
        float n = tanhf(xn + r * (hn + bh_n));
        float hnew = (1.f - z) * n + z * hp;

        // lanes kq<2 broadcast h_new to all 4 cluster CTAs (buffer 1-p)
        if (out_lane) {
            unsigned off = (unsigned)(((1 - p) * 8 + bsel) * RSTR + hpos) * 4u;
            unsigned hb = __float_as_uint(hnew);
            st_cluster_u32(pb[0] + off, hb);
            st_cluster_u32(pb[1] + off, hb);
            st_cluster_u32(pb[2] + off, hb);
            st_cluster_u32(pb[3] + off, hb);
        }

        cl_arrive();

        // overlapped with barrier: next-x prefetch + output store
        if (t + 1 < TT) {
            const float* xp = xrow + (size_t)(t + 1) * G3;
            xr = xp[h_glob]; xz = xp[256 + h_glob]; xn = xp[512 + h_glob];
        }
        if (out_lane) {
            if (layer0) {
                out_seq[((size_t)bglob * TT + t) * HH + h_glob] = hnew;
            } else if (t == TT - 1) {
                hT[bglob * HH + h_glob] = hnew;
            }
        }

        cl_wait();
        p ^= 1;
    }
}

// ---------------------------------------------------------------------------
// Launch helpers
// ---------------------------------------------------------------------------
static void launch_rec(const float* xg, const float* Whh, const float* bhh,
                       float* oseq, float* hT, int layer0)
{
    cudaFuncSetAttribute(gru_rec, cudaFuncAttributeMaxDynamicSharedMemorySize, REC_SMEM);
    cudaLaunchConfig_t cfg = {};
    cfg.gridDim = dim3(128, 1, 1);
    cfg.blockDim = dim3(1024, 1, 1);
    cfg.dynamicSmemBytes = REC_SMEM;
    cfg.stream = 0;
    cudaLaunchAttribute at[1];
    at[0].id = cudaLaunchAttributeClusterDimension;
    at[0].val.clusterDim.x = 4;
    at[0].val.clusterDim.y = 1;
    at[0].val.clusterDim.z = 1;
    cfg.attrs = at;
    cfg.numAttrs = 1;
    cudaLaunchKernelEx(&cfg, gru_rec, xg, Whh, bhh, oseq, hT, layer0);
}

extern "C" void kernel_launch(void* const* d_in, const int* in_sizes, int n_in,
                              void* d_out, int out_size)
{
    const float* x     = (const float*)d_in[0];
    const float* W_ih0 = (const float*)d_in[1];
    const float* W_hh0 = (const float*)d_in[2];
    const float* b_ih0 = (const float*)d_in[3];
    const float* b_hh0 = (const float*)d_in[4];
    const float* W_ih1 = (const float*)d_in[5];
    const float* W_hh1 = (const float*)d_in[6];
    const float* b_ih1 = (const float*)d_in[7];
    const float* b_hh1 = (const float*)d_in[8];
    const float* fc_W  = (const float*)d_in[9];
    const float* fc_b  = (const float*)d_in[10];
    float* out = (float*)d_out;

    float *xg, *o0, *hT, *xp, *wp;
    cudaGetSymbolAddress((void**)&xg, g_xg);
    cudaGetSymbolAddress((void**)&o0, g_out0);
    cudaGetSymbolAddress((void**)&hT, g_hT);
    cudaGetSymbolAddress((void**)&xp, g_xpad);
    cudaGetSymbolAddress((void**)&wp, g_wpad);

    const int M = BB * TT;  // 131072

    // 0) pad x and W_ih0 to K=80 so the vector GEMM path applies
    pad_k75<<<(M * KP + 255) / 256, 256>>>(x, xp, M);
    pad_k75<<<(G3 * KP + 255) / 256, 256>>>(W_ih0, wp, G3);
    // 1) xg0 = xpad @ wpad^T + b_ih0   (K = 80)
    gemm_tn_bias<<<dim3(M / 128, G3 / 128), 256>>>(xp, wp, b_ih0, xg, M, G3, KP);
    // 2) layer-0 recurrence -> out0 sequence
    launch_rec(xg, W_hh0, b_hh0, o0, nullptr, 1);
    // 3) xg1 = out0 @ W_ih1^T + b_ih1  (K = 256)
    gemm_tn_bias<<<dim3(M / 128, G3 / 128), 256>>>(o0, W_ih1, b_ih1, xg, M, G3, 256);
    // 4) layer-1 recurrence -> final hidden
    launch_rec(xg, W_hh1, b_hh1, nullptr, hT, 0);
    // 5) embedding = hT @ fc_W^T + fc_b
    gemm_tn_bias<<<dim3(BB / 128, HH / 128), 256>>>(hT, fc_W, fc_b, out, BB, HH, HH);
}

// round 7
// speedup vs baseline: 1.3775x; 1.3775x over previous
#include <cuda_runtime.h>
#include <cstdint>
#include <cstddef>

typedef unsigned long long ull;

#define DEV_INLINE __device__ __forceinline__

DEV_INLINE ull fma2(ull a, ull b, ull c) {
    ull d; asm("fma.rn.f32x2 %0, %1, %2, %3;" : "=l"(d) : "l"(a), "l"(b), "l"(c)); return d;
}
DEV_INLINE ull pack2(float lo, float hi) {
    ull r; asm("mov.b64 %0, {%1, %2};" : "=l"(r) : "f"(lo), "f"(hi)); return r;
}
DEV_INLINE float2 unpk(ull v) {
    float2 f; asm("mov.b64 {%0, %1}, %2;" : "=f"(f.x), "=f"(f.y) : "l"(v)); return f;
}
// fast sigmoid / tanh (MUFU rcp + ex2; rel err ~1e-6)
DEV_INLINE float sigm_(float x) { float e = __expf(-x); return __fdividef(1.f, 1.f + e); }
DEV_INLINE float tanh_(float a) { float t = __expf(-2.f * a); return __fdividef(1.f - t, 1.f + t); }

// ---------------------------------------------------------------------------
// Problem constants
// ---------------------------------------------------------------------------
#define BB 256   // batch
#define TT 512   // time
#define HH 256   // hidden
#define G3 768   // 3*H
#define KP 80    // padded IN_DIM (75 -> 80)

// ---------------------------------------------------------------------------
// Scratch (static device arrays; cudaMalloc forbidden)
// ---------------------------------------------------------------------------
__device__ float g_xg[(size_t)BB * TT * G3];    // input-gate preactivations
__device__ float g_out0[(size_t)BB * TT * HH];  // layer-0 output sequence
__device__ float g_hT[BB * HH];                 // final hidden of layer 1
__device__ float g_xpad[(size_t)BB * TT * KP];  // x padded to K=80
__device__ float g_wpad[G3 * KP];               // W_ih0 padded to K=80

// ---------------------------------------------------------------------------
// Padding pre-kernels
// ---------------------------------------------------------------------------
__global__ void pad_k75(const float* __restrict__ src, float* __restrict__ dst, int rows)
{
    int idx = blockIdx.x * blockDim.x + threadIdx.x;
    if (idx >= rows * KP) return;
    int r = idx / KP, c = idx - r * KP;
    dst[idx] = (c < 75) ? src[r * 75 + c] : 0.f;
}

// ---------------------------------------------------------------------------
// GEMM: C[M][N] = A[M][K] @ W[N][K]^T + bias[N]   (K % 4 == 0 required)
// 128x128 tile, BK=16, 256 threads, 8x8 microtile, f32x2 FMAs.  (unchanged)
// ---------------------------------------------------------------------------
__global__ __launch_bounds__(256, 2) void gemm_tn_bias(
    const float* __restrict__ A, const float* __restrict__ W,
    const float* __restrict__ bias, float* __restrict__ C,
    int M, int N, int K)
{
    __shared__ ull As2[16][130];
    __shared__ ull Bs2[16][68];

    const int tid = threadIdx.x;
    const int tm = tid >> 4;
    const int tn = tid & 15;
    const int mb = blockIdx.x * 128;
    const int nb = blockIdx.y * 128;

    const int lr = tid >> 1;
    const int lh = (tid & 1) * 8;
    const int pp = tid >> 2;
    const int pq = (tid & 3) * 4;

    ull acc[8][4];
#pragma unroll
    for (int i = 0; i < 8; ++i)
#pragma unroll
        for (int j = 0; j < 4; ++j) acc[i][j] = 0ull;

    for (int k0 = 0; k0 < K; k0 += 16) {
        const float* ap = A + (size_t)(mb + lr) * K + k0 + lh;
        float4 v0 = *(const float4*)(ap);
        float4 v1 = *(const float4*)(ap + 4);
        As2[lh + 0][lr] = pack2(v0.x, v0.x);
        As2[lh + 1][lr] = pack2(v0.y, v0.y);
        As2[lh + 2][lr] = pack2(v0.z, v0.z);
        As2[lh + 3][lr] = pack2(v0.w, v0.w);
        As2[lh + 4][lr] = pack2(v1.x, v1.x);
        As2[lh + 5][lr] = pack2(v1.y, v1.y);
        As2[lh + 6][lr] = pack2(v1.z, v1.z);
        As2[lh + 7][lr] = pack2(v1.w, v1.w);
        const float* wp0 = W + (size_t)(nb + 2 * pp) * K + k0 + pq;
        const float* wp1 = wp0 + K;
        float4 w0 = *(const float4*)wp0;
        float4 w1 = *(const float4*)wp1;
        Bs2[pq + 0][pp] = pack2(w0.x, w1.x);
        Bs2[pq + 1][pp] = pack2(w0.y, w1.y);
        Bs2[pq + 2][pp] = pack2(w0.z, w1.z);
        Bs2[pq + 3][pp] = pack2(w0.w, w1.w);
        __syncthreads();
#pragma unroll
        for (int k = 0; k < 16; ++k) {
            ulonglong2 a01 = *(const ulonglong2*)&As2[k][8 * tm];
            ulonglong2 a23 = *(const ulonglong2*)&As2[k][8 * tm + 2];
            ulonglong2 a45 = *(const ulonglong2*)&As2[k][8 * tm + 4];
            ulonglong2 a67 = *(const ulonglong2*)&As2[k][8 * tm + 6];
            ulonglong2 b01 = *(const ulonglong2*)&Bs2[k][2 * tn];
            ulonglong2 b23 = *(const ulonglong2*)&Bs2[k][32 + 2 * tn];
            ull b0 = b01.x, b1 = b01.y, b2 = b23.x, b3 = b23.y;
            acc[0][0] = fma2(a01.x, b0, acc[0][0]); acc[0][1] = fma2(a01.x, b1, acc[0][1]);
            acc[0][2] = fma2(a01.x, b2, acc[0][2]); acc[0][3] = fma2(a01.x, b3, acc[0][3]);
            acc[1][0] = fma2(a01.y, b0, acc[1][0]); acc[1][1] = fma2(a01.y, b1, acc[1][1]);
            acc[1][2] = fma2(a01.y, b2, acc[1][2]); acc[1][3] = fma2(a01.y, b3, acc[1][3]);
            acc[2][0] = fma2(a23.x, b0, acc[2][0]); acc[2][1] = fma2(a23.x, b1, acc[2][1]);
            acc[2][2] = fma2(a23.x, b2, acc[2][2]); acc[2][3] = fma2(a23.x, b3, acc[2][3]);
            acc[3][0] = fma2(a23.y, b0, acc[3][0]); acc[3][1] = fma2(a23.y, b1, acc[3][1]);
            acc[3][2] = fma2(a23.y, b2, acc[3][2]); acc[3][3] = fma2(a23.y, b3, acc[3][3]);
            acc[4][0] = fma2(a45.x, b0, acc[4][0]); acc[4][1] = fma2(a45.x, b1, acc[4][1]);
            acc[4][2] = fma2(a45.x, b2, acc[4][2]); acc[4][3] = fma2(a45.x, b3, acc[4][3]);
            acc[5][0] = fma2(a45.y, b0, acc[5][0]); acc[5][1] = fma2(a45.y, b1, acc[5][1]);
            acc[5][2] = fma2(a45.y, b2, acc[5][2]); acc[5][3] = fma2(a45.y, b3, acc[5][3]);
            acc[6][0] = fma2(a67.x, b0, acc[6][0]); acc[6][1] = fma2(a67.x, b1, acc[6][1]);
            acc[6][2] = fma2(a67.x, b2, acc[6][2]); acc[6][3] = fma2(a67.x, b3, acc[6][3]);
            acc[7][0] = fma2(a67.y, b0, acc[7][0]); acc[7][1] = fma2(a67.y, b1, acc[7][1]);
            acc[7][2] = fma2(a67.y, b2, acc[7][2]); acc[7][3] = fma2(a67.y, b3, acc[7][3]);
        }
        __syncthreads();
    }

    float4 bb0 = *(const float4*)(bias + nb + 4 * tn);
    float4 bb1 = *(const float4*)(bias + nb + 64 + 4 * tn);
#pragma unroll
    for (int i = 0; i < 8; ++i) {
        float* crow = C + (size_t)(mb + 8 * tm + i) * N + nb;
        float2 p0 = unpk(acc[i][0]), p1 = unpk(acc[i][1]);
        float2 p2 = unpk(acc[i][2]), p3 = unpk(acc[i][3]);
        float4 o0; o0.x = p0.x + bb0.x; o0.y = p0.y + bb0.y; o0.z = p1.x + bb0.z; o0.w = p1.y + bb0.w;
        float4 o1; o1.x = p2.x + bb1.x; o1.y = p2.y + bb1.y; o1.z = p3.x + bb1.z; o1.w = p3.y + bb1.w;
        *(float4*)(crow + 4 * tn)      = o0;
        *(float4*)(crow + 64 + 4 * tn) = o1;
    }
}

// ---------------------------------------------------------------------------
// GRU recurrence: 32 clusters x 4 CTAs, 512 threads/CTA (R5 layout — the
// wavefront-optimal mapping: 8 distinct 16B addrs per LDS.128, 4 lanes/addr).
// Thread = (h_local 0..63) x (bp 0..3) x (ks 0..1): 1 hidden unit,
// 2 batches (bp, bp+4), half of k.  3-shuffle cross-half merge.
// ---------------------------------------------------------------------------
#define RSTR 264
#define REC_W_FLOATS (192 * RSTR)
#define REC_SMEM ((192 * RSTR + 2 * 8 * RSTR) * 4)   // 219648 B

DEV_INLINE unsigned ctarank() { unsigned r; asm("mov.u32 %0, %%cluster_ctarank;" : "=r"(r)); return r; }
DEV_INLINE unsigned s2u(const void* p) {
    unsigned a;
    asm("{ .reg .u64 t; cvta.to.shared.u64 t, %1; cvt.u32.u64 %0, t; }" : "=r"(a) : "l"(p));
    return a;
}
DEV_INLINE unsigned mapa_(unsigned a, unsigned r) {
    unsigned o; asm("mapa.shared::cluster.u32 %0, %1, %2;" : "=r"(o) : "r"(a), "r"(r)); return o;
}
DEV_INLINE void st_cluster_u32(unsigned addr, unsigned v) {
    asm volatile("st.shared::cluster.u32 [%0], %1;" :: "r"(addr), "r"(v) : "memory");
}
DEV_INLINE void cl_arrive() { asm volatile("barrier.cluster.arrive.aligned;" ::: "memory"); }
DEV_INLINE void cl_wait()   { asm volatile("barrier.cluster.wait.aligned;"   ::: "memory"); }

__global__ __launch_bounds__(512, 1) void gru_rec(
    const float* __restrict__ xg, const float* __restrict__ W_hh,
    const float* __restrict__ b_hh, float* __restrict__ out_seq,
    float* __restrict__ hT, int layer0)
{
    extern __shared__ float smem[];
    float* w = smem;                        // [192 rows][264]  k in [0..127],[132..259]
    float* hbase = smem + REC_W_FLOATS;     // [2 bufs][8 batches][264]

    const int tid = threadIdx.x;
    const unsigned rank = ctarank();
    const int cid = blockIdx.x >> 2;        // cluster 0..31
    const int h_local = tid >> 3;           // 0..63
    const int bp = (tid >> 1) & 3;          // 0..3
    const int ks = tid & 1;                 // k-half
    const int h_glob = (int)rank * 64 + h_local;
    const int bsel = bp + 4 * ks;           // batch this lane finalizes
    const int bglob = cid * 8 + bsel;
    const int hpoff = h_glob + ((h_glob >= 128) ? 4 : 0);  // h position in split row

    // Load W_hh slice: smem row g*64+h <- global row g*256 + rank*64 + h
    for (int i = tid; i < 192 * 64; i += 512) {
        int row = i >> 6, kk = (i & 63) * 4;
        int grow = (row >> 6) * 256 + (int)rank * 64 + (row & 63);
        float4 v = ((const float4*)W_hh)[(size_t)grow * 64 + (kk >> 2)];
        *(float4*)(w + row * RSTR + kk + ((kk >= 128) ? 4 : 0)) = v;
    }
    for (int i = tid; i < 8 * RSTR; i += 512) hbase[i] = 0.f;  // h buffer 0 = 0

    const float bh_r = b_hh[h_glob];
    const float bh_z = b_hh[256 + h_glob];
    const float bh_n = b_hh[512 + h_glob];

    __syncthreads();
    cl_arrive(); cl_wait();

    unsigned hbase_u = s2u(hbase);
    unsigned pb[4];
#pragma unroll
    for (int q = 0; q < 4; ++q) pb[q] = mapa_(hbase_u, (unsigned)q);

    const int ko = ks * 132;                // k-half offset in a row
    const float* wr = w + h_local * RSTR + ko;
    const float* wz = wr + 64 * RSTR;
    const float* wn = wr + 128 * RSTR;

    const float* xrow = xg + (size_t)bglob * TT * G3;
    float xr = xrow[h_glob], xz = xrow[256 + h_glob], xn = xrow[512 + h_glob];

    int p = 0;
    for (int t = 0; t < TT; ++t) {
        const float* h0r = hbase + (p * 8 + bp) * RSTR + ko;       // batch bp
        const float* h1r = h0r + 4 * RSTR;                          // batch bp+4

        // hoist hp load: hide its 29-cyc LDS latency under the k-loop
        float hp = hbase[(p * 8 + bsel) * RSTR + hpoff];

        ull ar0 = 0, az0 = 0, an0 = 0, ar1 = 0, az1 = 0, an1 = 0;
#pragma unroll 16
        for (int k4 = 0; k4 < 32; ++k4) {
            ulonglong2 wrv = *(const ulonglong2*)(wr + 4 * k4);
            ulonglong2 wzv = *(const ulonglong2*)(wz + 4 * k4);
            ulonglong2 wnv = *(const ulonglong2*)(wn + 4 * k4);
            ulonglong2 h0v = *(const ulonglong2*)(h0r + 4 * k4);
            ulonglong2 h1v = *(const ulonglong2*)(h1r + 4 * k4);
            ar0 = fma2(wrv.x, h0v.x, ar0); ar0 = fma2(wrv.y, h0v.y, ar0);
            az0 = fma2(wzv.x, h0v.x, az0); az0 = fma2(wzv.y, h0v.y, az0);
            an0 = fma2(wnv.x, h0v.x, an0); an0 = fma2(wnv.y, h0v.y, an0);
            ar1 = fma2(wrv.x, h1v.x, ar1); ar1 = fma2(wrv.y, h1v.y, ar1);
            az1 = fma2(wzv.x, h1v.x, az1); az1 = fma2(wzv.y, h1v.y, az1);
            an1 = fma2(wnv.x, h1v.x, an1); an1 = fma2(wnv.y, h1v.y, an1);
        }
        float2 s;
        s = unpk(ar0); float fr0 = s.x + s.y;
        s = unpk(az0); float fz0 = s.x + s.y;
        s = unpk(an0); float fn0 = s.x + s.y;
        s = unpk(ar1); float fr1 = s.x + s.y;
        s = unpk(az1); float fz1 = s.x + s.y;
        s = unpk(an1); float fn1 = s.x + s.y;

        // 3-shuffle merge: send the partial the PARTNER (lane^1) needs.
        // lane ks finalizes batch (bp + 4*ks): needs own frK + partner frK.
        float sr = ks ? fr0 : fr1;
        float sz = ks ? fz0 : fz1;
        float sn = ks ? fn0 : fn1;
        float rr = __shfl_xor_sync(0xffffffffu, sr, 1);
        float rz = __shfl_xor_sync(0xffffffffu, sz, 1);
        float rn = __shfl_xor_sync(0xffffffffu, sn, 1);
        float hr = (ks ? fr1 : fr0) + rr;
        float hz = (ks ? fz1 : fz0) + rz;
        float hn = (ks ? fn1 : fn0) + rn;

        float r = sigm_(xr + bh_r + hr);
        float z = sigm_(xz + bh_z + hz);
        float n = tanh_(xn + r * (hn + bh_n));
        float hnew = (1.f - z) * n + z * hp;

        // broadcast to all 4 cluster CTAs (buffer 1-p)
        unsigned off = (unsigned)(((1 - p) * 8 + bsel) * RSTR + hpoff) * 4u;
        unsigned hb = __float_as_uint(hnew);
        st_cluster_u32(pb[0] + off, hb);
        st_cluster_u32(pb[1] + off, hb);
        st_cluster_u32(pb[2] + off, hb);
        st_cluster_u32(pb[3] + off, hb);

        cl_arrive();

        // overlapped with barrier: next-x prefetch + output store
        if (t + 1 < TT) {
            const float* xp = xrow + (size_t)(t + 1) * G3;
            xr = xp[h_glob]; xz = xp[256 + h_glob]; xn = xp[512 + h_glob];
        }
        if (layer0) {
            out_seq[((size_t)bglob * TT + t) * HH + h_glob] = hnew;
        } else if (t == TT - 1) {
            hT[bglob * HH + h_glob] = hnew;
        }

        cl_wait();
        p ^= 1;
    }
}

// ---------------------------------------------------------------------------
// Launch helpers
// ---------------------------------------------------------------------------
static void launch_rec(const float* xg, const float* Whh, const float* bhh,
                       float* oseq, float* hT, int layer0)
{
    cudaFuncSetAttribute(gru_rec, cudaFuncAttributeMaxDynamicSharedMemorySize, REC_SMEM);
    cudaLaunchConfig_t cfg = {};
    cfg.gridDim = dim3(128, 1, 1);
    cfg.blockDim = dim3(512, 1, 1);
    cfg.dynamicSmemBytes = REC_SMEM;
    cfg.stream = 0;
    cudaLaunchAttribute at[1];
    at[0].id = cudaLaunchAttributeClusterDimension;
    at[0].val.clusterDim.x = 4;
    at[0].val.clusterDim.y = 1;
    at[0].val.clusterDim.z = 1;
    cfg.attrs = at;
    cfg.numAttrs = 1;
    cudaLaunchKernelEx(&cfg, gru_rec, xg, Whh, bhh, oseq, hT, layer0);
}

extern "C" void kernel_launch(void* const* d_in, const int* in_sizes, int n_in,
                              void* d_out, int out_size)
{
    const float* x     = (const float*)d_in[0];
    const float* W_ih0 = (const float*)d_in[1];
    const float* W_hh0 = (const float*)d_in[2];
    const float* b_ih0 = (const float*)d_in[3];
    const float* b_hh0 = (const float*)d_in[4];
    const float* W_ih1 = (const float*)d_in[5];
    const float* W_hh1 = (const float*)d_in[6];
    const float* b_ih1 = (const float*)d_in[7];
    const float* b_hh1 = (const float*)d_in[8];
    const float* fc_W  = (const float*)d_in[9];
    const float* fc_b  = (const float*)d_in[10];
    float* out = (float*)d_out;

    float *xg, *o0, *hT, *xp, *wp;
    cudaGetSymbolAddress((void**)&xg, g_xg);
    cudaGetSymbolAddress((void**)&o0, g_out0);
    cudaGetSymbolAddress((void**)&hT, g_hT);
    cudaGetSymbolAddress((void**)&xp, g_xpad);
    cudaGetSymbolAddress((void**)&wp, g_wpad);

    const int M = BB * TT;  // 131072

    // 0) pad x and W_ih0 to K=80 so the vector GEMM path applies
    pad_k75<<<(M * KP + 255) / 256, 256>>>(x, xp, M);
    pad_k75<<<(G3 * KP + 255) / 256, 256>>>(W_ih0, wp, G3);
    // 1) xg0 = xpad @ wpad^T + b_ih0   (K = 80)
    gemm_tn_bias<<<dim3(M / 128, G3 / 128), 256>>>(xp, wp, b_ih0, xg, M, G3, KP);
    // 2) layer-0 recurrence -> out0 sequence
    launch_rec(xg, W_hh0, b_hh0, o0, nullptr, 1);
    // 3) xg1 = out0 @ W_ih1^T + b_ih1  (K = 256)
    gemm_tn_bias<<<dim3(M / 128, G3 / 128), 256>>>(o0, W_ih1, b_ih1, xg, M, G3, 256);
    // 4) layer-1 recurrence -> final hidden
    launch_rec(xg, W_hh1, b_hh1, nullptr, hT, 0);
    // 5) embedding = hT @ fc_W^T + fc_b
    gemm_tn_bias<<<dim3(BB / 128, HH / 128), 256>>>(hT, fc_W, fc_b, out, BB, HH, HH);
}

// round 8
// speedup vs baseline: 1.5824x; 1.1487x over previous
#include <cuda_runtime.h>
#include <cstdint>
#include <cstddef>

typedef unsigned long long ull;

#define DEV_INLINE __device__ __forceinline__

DEV_INLINE ull fma2(ull a, ull b, ull c) {
    ull d; asm("fma.rn.f32x2 %0, %1, %2, %3;" : "=l"(d) : "l"(a), "l"(b), "l"(c)); return d;
}
DEV_INLINE float2 unpk(ull v) {
    float2 f; asm("mov.b64 {%0, %1}, %2;" : "=f"(f.x), "=f"(f.y) : "l"(v)); return f;
}
DEV_INLINE unsigned tf32_(float x) {
    unsigned r; asm("cvt.rna.tf32.f32 %0, %1;" : "=r"(r) : "f"(x)); return r;
}
// fast sigmoid / tanh (MUFU rcp + ex2; rel err ~1e-6)
DEV_INLINE float sigm_(float x) { float e = __expf(-x); return __fdividef(1.f, 1.f + e); }
DEV_INLINE float tanh_(float a) { float t = __expf(-2.f * a); return __fdividef(1.f - t, 1.f + t); }

// ---------------------------------------------------------------------------
// Problem constants
// ---------------------------------------------------------------------------
#define BB 256   // batch
#define TT 512   // time
#define HH 256   // hidden
#define G3 768   // 3*H
#define KP 80    // padded IN_DIM (75 -> 80)

// ---------------------------------------------------------------------------
// Scratch (static device arrays; cudaMalloc forbidden)
// ---------------------------------------------------------------------------
__device__ float g_xg[(size_t)BB * TT * G3];    // input-gate preactivations
__device__ float g_out0[(size_t)BB * TT * HH];  // layer-0 output sequence
__device__ float g_hT[BB * HH];                 // final hidden of layer 1
__device__ float g_xpad[(size_t)BB * TT * KP];  // x padded to K=80
__device__ float g_wpad[G3 * KP];               // W_ih0 padded to K=80

// ---------------------------------------------------------------------------
// Padding pre-kernels
// ---------------------------------------------------------------------------
__global__ void pad_k75(const float* __restrict__ src, float* __restrict__ dst, int rows)
{
    int idx = blockIdx.x * blockDim.x + threadIdx.x;
    if (idx >= rows * KP) return;
    int r = idx / KP, c = idx - r * KP;
    dst[idx] = (c < 75) ? src[r * 75 + c] : 0.f;
}

// ---------------------------------------------------------------------------
// tf32 tensor-core GEMM: C[M][N] = A[M][K] @ W[N][K]^T + bias[N]
// (K % 16 == 0 required.)  128x128 tile, BK=16, 256 threads = 8 warps
// in a 2(m) x 4(n) grid; per warp 4x4 m16n8k8 atoms (64x32).
// Smem stride 136 -> all fragment LDS.32 conflict-free.
// ---------------------------------------------------------------------------
#define TSTR 136

__global__ __launch_bounds__(256, 2) void gemm_tf32(
    const float* __restrict__ A, const float* __restrict__ W,
    const float* __restrict__ bias, float* __restrict__ C,
    int M, int N, int K)
{
    __shared__ unsigned As[16][TSTR];  // [k][m] tf32 bits
    __shared__ unsigned Bs[16][TSTR];  // [k][n] tf32 bits

    const int tid = threadIdx.x;
    const int lane = tid & 31;
    const int wid = tid >> 5;
    const int wm = wid & 1;          // warp m: 0..1 (64 rows each)
    const int wn = wid >> 1;         // warp n: 0..3 (32 cols each)
    const int g  = lane >> 2;        // group 0..7
    const int tg = lane & 3;         // thread-in-group 0..3
    const int mb = blockIdx.x * 128;
    const int nb = blockIdx.y * 128;

    const int fr = tid >> 1;         // fill row 0..127
    const int fk = (tid & 1) * 8;    // fill k offset 0/8

    float c[4][4][4];                // [matom][natom][frag]
#pragma unroll
    for (int i = 0; i < 4; ++i)
#pragma unroll
        for (int j = 0; j < 4; ++j)
#pragma unroll
            for (int q = 0; q < 4; ++q) c[i][j][q] = 0.f;

    for (int k0 = 0; k0 < K; k0 += 16) {
        // ---- fill (convert fp32 -> tf32) ----
        {
            const float* ap = A + (size_t)(mb + fr) * K + k0 + fk;
            float4 a0 = *(const float4*)(ap);
            float4 a1 = *(const float4*)(ap + 4);
            As[fk + 0][fr] = tf32_(a0.x);
            As[fk + 1][fr] = tf32_(a0.y);
            As[fk + 2][fr] = tf32_(a0.z);
            As[fk + 3][fr] = tf32_(a0.w);
            As[fk + 4][fr] = tf32_(a1.x);
            As[fk + 5][fr] = tf32_(a1.y);
            As[fk + 6][fr] = tf32_(a1.z);
            As[fk + 7][fr] = tf32_(a1.w);
            const float* wp = W + (size_t)(nb + fr) * K + k0 + fk;
            float4 w0 = *(const float4*)(wp);
            float4 w1 = *(const float4*)(wp + 4);
            Bs[fk + 0][fr] = tf32_(w0.x);
            Bs[fk + 1][fr] = tf32_(w0.y);
            Bs[fk + 2][fr] = tf32_(w0.z);
            Bs[fk + 3][fr] = tf32_(w0.w);
            Bs[fk + 4][fr] = tf32_(w1.x);
            Bs[fk + 5][fr] = tf32_(w1.y);
            Bs[fk + 6][fr] = tf32_(w1.z);
            Bs[fk + 7][fr] = tf32_(w1.w);
        }
        __syncthreads();

#pragma unroll
        for (int ks = 0; ks < 2; ++ks) {
            const int kk = ks * 8;
            // B fragments: b0 = B[k=tg][n], b1 = B[k=tg+4][n]
            unsigned bf[4][2];
#pragma unroll
            for (int j = 0; j < 4; ++j) {
                int cb = wn * 32 + j * 8 + g;
                bf[j][0] = Bs[kk + tg][cb];
                bf[j][1] = Bs[kk + tg + 4][cb];
            }
#pragma unroll
            for (int i = 0; i < 4; ++i) {
                int rb = wm * 64 + i * 16;
                unsigned a0 = As[kk + tg][rb + g];
                unsigned a1 = As[kk + tg][rb + g + 8];
                unsigned a2 = As[kk + tg + 4][rb + g];
                unsigned a3 = As[kk + tg + 4][rb + g + 8];
#pragma unroll
                for (int j = 0; j < 4; ++j) {
                    asm("mma.sync.aligned.m16n8k8.row.col.f32.tf32.tf32.f32 "
                        "{%0,%1,%2,%3}, {%4,%5,%6,%7}, {%8,%9}, {%0,%1,%2,%3};"
                        : "+f"(c[i][j][0]), "+f"(c[i][j][1]),
                          "+f"(c[i][j][2]), "+f"(c[i][j][3])
                        : "r"(a0), "r"(a1), "r"(a2), "r"(a3),
                          "r"(bf[j][0]), "r"(bf[j][1]));
                }
            }
        }
        __syncthreads();
    }

    // ---- epilogue ----
#pragma unroll
    for (int j = 0; j < 4; ++j) {
        int col = nb + wn * 32 + j * 8 + 2 * tg;
        float2 bb = *(const float2*)(bias + col);
#pragma unroll
        for (int i = 0; i < 4; ++i) {
            int row = mb + wm * 64 + i * 16 + g;
            float2 v0; v0.x = c[i][j][0] + bb.x; v0.y = c[i][j][1] + bb.y;
            float2 v1; v1.x = c[i][j][2] + bb.x; v1.y = c[i][j][3] + bb.y;
            *(float2*)(C + (size_t)row * N + col)       = v0;
            *(float2*)(C + (size_t)(row + 8) * N + col) = v1;
        }
    }
}

// ---------------------------------------------------------------------------
// GRU recurrence: unchanged from R7 (best known).
// ---------------------------------------------------------------------------
#define RSTR 264
#define REC_W_FLOATS (192 * RSTR)
#define REC_SMEM ((192 * RSTR + 2 * 8 * RSTR) * 4)   // 219648 B

DEV_INLINE unsigned ctarank() { unsigned r; asm("mov.u32 %0, %%cluster_ctarank;" : "=r"(r)); return r; }
DEV_INLINE unsigned s2u(const void* p) {
    unsigned a;
    asm("{ .reg .u64 t; cvta.to.shared.u64 t, %1; cvt.u32.u64 %0, t; }" : "=r"(a) : "l"(p));
    return a;
}
DEV_INLINE unsigned mapa_(unsigned a, unsigned r) {
    unsigned o; asm("mapa.shared::cluster.u32 %0, %1, %2;" : "=r"(o) : "r"(a), "r"(r)); return o;
}
DEV_INLINE void st_cluster_u32(unsigned addr, unsigned v) {
    asm volatile("st.shared::cluster.u32 [%0], %1;" :: "r"(addr), "r"(v) : "memory");
}
DEV_INLINE void cl_arrive() { asm volatile("barrier.cluster.arrive.aligned;" ::: "memory"); }
DEV_INLINE void cl_wait()   { asm volatile("barrier.cluster.wait.aligned;"   ::: "memory"); }

__global__ __launch_bounds__(512, 1) void gru_rec(
    const float* __restrict__ xg, const float* __restrict__ W_hh,
    const float* __restrict__ b_hh, float* __restrict__ out_seq,
    float* __restrict__ hT, int layer0)
{
    extern __shared__ float smem[];
    float* w = smem;                        // [192 rows][264]
    float* hbase = smem + REC_W_FLOATS;     // [2 bufs][8 batches][264]

    const int tid = threadIdx.x;
    const unsigned rank = ctarank();
    const int cid = blockIdx.x >> 2;
    const int h_local = tid >> 3;
    const int bp = (tid >> 1) & 3;
    const int ks = tid & 1;
    const int h_glob = (int)rank * 64 + h_local;
    const int bsel = bp + 4 * ks;
    const int bglob = cid * 8 + bsel;
    const int hpoff = h_glob + ((h_glob >= 128) ? 4 : 0);

    for (int i = tid; i < 192 * 64; i += 512) {
        int row = i >> 6, kk = (i & 63) * 4;
        int grow = (row >> 6) * 256 + (int)rank * 64 + (row & 63);
        float4 v = ((const float4*)W_hh)[(size_t)grow * 64 + (kk >> 2)];
        *(float4*)(w + row * RSTR + kk + ((kk >= 128) ? 4 : 0)) = v;
    }
    for (int i = tid; i < 8 * RSTR; i += 512) hbase[i] = 0.f;

    const float bh_r = b_hh[h_glob];
    const float bh_z = b_hh[256 + h_glob];
    const float bh_n = b_hh[512 + h_glob];

    __syncthreads();
    cl_arrive(); cl_wait();

    unsigned hbase_u = s2u(hbase);
    unsigned pb[4];
#pragma unroll
    for (int q = 0; q < 4; ++q) pb[q] = mapa_(hbase_u, (unsigned)q);

    const int ko = ks * 132;
    const float* wr = w + h_local * RSTR + ko;
    const float* wz = wr + 64 * RSTR;
    const float* wn = wr + 128 * RSTR;

    const float* xrow = xg + (size_t)bglob * TT * G3;
    float xr = xrow[h_glob], xz = xrow[256 + h_glob], xn = xrow[512 + h_glob];

    int p = 0;
    for (int t = 0; t < TT; ++t) {
        const float* h0r = hbase + (p * 8 + bp) * RSTR + ko;
        const float* h1r = h0r + 4 * RSTR;

        float hp = hbase[(p * 8 + bsel) * RSTR + hpoff];

        ull ar0 = 0, az0 = 0, an0 = 0, ar1 = 0, az1 = 0, an1 = 0;
#pragma unroll 16
        for (int k4 = 0; k4 < 32; ++k4) {
            ulonglong2 wrv = *(const ulonglong2*)(wr + 4 * k4);
            ulonglong2 wzv = *(const ulonglong2*)(wz + 4 * k4);
            ulonglong2 wnv = *(const ulonglong2*)(wn + 4 * k4);
            ulonglong2 h0v = *(const ulonglong2*)(h0r + 4 * k4);
            ulonglong2 h1v = *(const ulonglong2*)(h1r + 4 * k4);
            ar0 = fma2(wrv.x, h0v.x, ar0); ar0 = fma2(wrv.y, h0v.y, ar0);
            az0 = fma2(wzv.x, h0v.x, az0); az0 = fma2(wzv.y, h0v.y, az0);
            an0 = fma2(wnv.x, h0v.x, an0); an0 = fma2(wnv.y, h0v.y, an0);
            ar1 = fma2(wrv.x, h1v.x, ar1); ar1 = fma2(wrv.y, h1v.y, ar1);
            az1 = fma2(wzv.x, h1v.x, az1); az1 = fma2(wzv.y, h1v.y, az1);
            an1 = fma2(wnv.x, h1v.x, an1); an1 = fma2(wnv.y, h1v.y, an1);
        }
        float2 s;
        s = unpk(ar0); float fr0 = s.x + s.y;
        s = unpk(az0); float fz0 = s.x + s.y;
        s = unpk(an0); float fn0 = s.x + s.y;
        s = unpk(ar1); float fr1 = s.x + s.y;
        s = unpk(az1); float fz1 = s.x + s.y;
        s = unpk(an1); float fn1 = s.x + s.y;

        float sr = ks ? fr0 : fr1;
        float sz = ks ? fz0 : fz1;
        float sn = ks ? fn0 : fn1;
        float rr = __shfl_xor_sync(0xffffffffu, sr, 1);
        float rz = __shfl_xor_sync(0xffffffffu, sz, 1);
        float rn = __shfl_xor_sync(0xffffffffu, sn, 1);
        float hr = (ks ? fr1 : fr0) + rr;
        float hz = (ks ? fz1 : fz0) + rz;
        float hn = (ks ? fn1 : fn0) + rn;

        float r = sigm_(xr + bh_r + hr);
        float z = sigm_(xz + bh_z + hz);
        float n = tanh_(xn + r * (hn + bh_n));
        float hnew = (1.f - z) * n + z * hp;

        unsigned off = (unsigned)(((1 - p) * 8 + bsel) * RSTR + hpoff) * 4u;
        unsigned hb = __float_as_uint(hnew);
        st_cluster_u32(pb[0] + off, hb);
        st_cluster_u32(pb[1] + off, hb);
        st_cluster_u32(pb[2] + off, hb);
        st_cluster_u32(pb[3] + off, hb);

        cl_arrive();

        if (t + 1 < TT) {
            const float* xp = xrow + (size_t)(t + 1) * G3;
            xr = xp[h_glob]; xz = xp[256 + h_glob]; xn = xp[512 + h_glob];
        }
        if (layer0) {
            out_seq[((size_t)bglob * TT + t) * HH + h_glob] = hnew;
        } else if (t == TT - 1) {
            hT[bglob * HH + h_glob] = hnew;
        }

        cl_wait();
        p ^= 1;
    }
}

// ---------------------------------------------------------------------------
// Launch helpers
// ---------------------------------------------------------------------------
static void launch_rec(const float* xg, const float* Whh, const float* bhh,
                       float* oseq, float* hT, int layer0)
{
    cudaFuncSetAttribute(gru_rec, cudaFuncAttributeMaxDynamicSharedMemorySize, REC_SMEM);
    cudaLaunchConfig_t cfg = {};
    cfg.gridDim = dim3(128, 1, 1);
    cfg.blockDim = dim3(512, 1, 1);
    cfg.dynamicSmemBytes = REC_SMEM;
    cfg.stream = 0;
    cudaLaunchAttribute at[1];
    at[0].id = cudaLaunchAttributeClusterDimension;
    at[0].val.clusterDim.x = 4;
    at[0].val.clusterDim.y = 1;
    at[0].val.clusterDim.z = 1;
    cfg.attrs = at;
    cfg.numAttrs = 1;
    cudaLaunchKernelEx(&cfg, gru_rec, xg, Whh, bhh, oseq, hT, layer0);
}

extern "C" void kernel_launch(void* const* d_in, const int* in_sizes, int n_in,
                              void* d_out, int out_size)
{
    const float* x     = (const float*)d_in[0];
    const float* W_ih0 = (const float*)d_in[1];
    const float* W_hh0 = (const float*)d_in[2];
    const float* b_ih0 = (const float*)d_in[3];
    const float* b_hh0 = (const float*)d_in[4];
    const float* W_ih1 = (const float*)d_in[5];
    const float* W_hh1 = (const float*)d_in[6];
    const float* b_ih1 = (const float*)d_in[7];
    const float* b_hh1 = (const float*)d_in[8];
    const float* fc_W  = (const float*)d_in[9];
    const float* fc_b  = (const float*)d_in[10];
    float* out = (float*)d_out;

    float *xg, *o0, *hT, *xp, *wp;
    cudaGetSymbolAddress((void**)&xg, g_xg);
    cudaGetSymbolAddress((void**)&o0, g_out0);
    cudaGetSymbolAddress((void**)&hT, g_hT);
    cudaGetSymbolAddress((void**)&xp, g_xpad);
    cudaGetSymbolAddress((void**)&wp, g_wpad);

    const int M = BB * TT;  // 131072

    // 0) pad x and W_ih0 to K=80
    pad_k75<<<(M * KP + 255) / 256, 256>>>(x, xp, M);
    pad_k75<<<(G3 * KP + 255) / 256, 256>>>(W_ih0, wp, G3);
    // 1) xg0 = xpad @ wpad^T + b_ih0   (K = 80)
    gemm_tf32<<<dim3(M / 128, G3 / 128), 256>>>(xp, wp, b_ih0, xg, M, G3, KP);
    // 2) layer-0 recurrence -> out0 sequence
    launch_rec(xg, W_hh0, b_hh0, o0, nullptr, 1);
    // 3) xg1 = out0 @ W_ih1^T + b_ih1  (K = 256)
    gemm_tf32<<<dim3(M / 128, G3 / 128), 256>>>(o0, W_ih1, b_ih1, xg, M, G3, 256);
    // 4) layer-1 recurrence -> final hidden
    launch_rec(xg, W_hh1, b_hh1, nullptr, hT, 0);
    // 5) embedding = hT @ fc_W^T + fc_b
    gemm_tf32<<<dim3(BB / 128, HH / 128), 256>>>(hT, fc_W, fc_b, out, BB, HH, HH);
}